// round 16
// baseline (speedup 1.0000x reference)
#include <cuda_runtime.h>
#include <cuda_bf16.h>
#include <cstdint>
#include <stdint.h>
#include <math.h>

#define B_ 2
#define S_ 2048
#define D_ 1024
#define H_ 16
#define HD 64
#define BH_ (B_*H_)
#define KAD 128
#define MROWS (B_*S_)
#define MSHIFT 16.0f

typedef __nv_bfloat16 bf16;

// ---- scratch (static device arrays; no allocation allowed) ----
__device__ bf16 g_xh[MROWS * D_], g_xl[MROWS * D_];
__device__ bf16 g_wqh[D_*D_], g_wql[D_*D_];
__device__ bf16 g_wkh[D_*D_], g_wkl[D_*D_];
__device__ bf16 g_wvh[D_*D_], g_wvl[D_*D_];
__device__ bf16 g_woh[D_*D_], g_wol[D_*D_];
__device__ bf16 g_qah[BH_*S_*KAD], g_qal[BH_*S_*KAD];
__device__ bf16 g_kah[BH_*S_*KAD], g_kal[BH_*S_*KAD];
__device__ bf16 g_vh[MROWS * D_], g_vl[MROWS * D_];
__device__ bf16 g_mh[MROWS * D_], g_ml[MROWS * D_];

// ---- mma / ldmatrix / cp.async helpers ----
__device__ __forceinline__ void ldsm4(uint32_t addr, uint32_t r[4]) {
  asm volatile("ldmatrix.sync.aligned.m8n8.x4.shared.b16 {%0,%1,%2,%3},[%4];"
    : "=r"(r[0]),"=r"(r[1]),"=r"(r[2]),"=r"(r[3]) : "r"(addr));
}
__device__ __forceinline__ void ldsm4t(uint32_t addr, uint32_t r[4]) {
  asm volatile("ldmatrix.sync.aligned.m8n8.x4.trans.shared.b16 {%0,%1,%2,%3},[%4];"
    : "=r"(r[0]),"=r"(r[1]),"=r"(r[2]),"=r"(r[3]) : "r"(addr));
}
__device__ __forceinline__ void mma_bf16(float c[4], const uint32_t a[4], const uint32_t b[2]) {
  asm("mma.sync.aligned.m16n8k16.row.col.f32.bf16.bf16.f32 "
    "{%0,%1,%2,%3},{%4,%5,%6,%7},{%8,%9},{%0,%1,%2,%3};"
    : "+f"(c[0]),"+f"(c[1]),"+f"(c[2]),"+f"(c[3])
    : "r"(a[0]),"r"(a[1]),"r"(a[2]),"r"(a[3]),"r"(b[0]),"r"(b[1]));
}
__device__ __forceinline__ uint32_t packbf(float lo, float hi) {
  uint32_t r;
  asm("cvt.rn.bf16x2.f32 %0, %1, %2;" : "=r"(r) : "f"(hi), "f"(lo));
  return r;
}
__device__ __forceinline__ void cpasync16(uint32_t dst, const void* src) {
  asm volatile("cp.async.cg.shared.global [%0], [%1], 16;" :: "r"(dst), "l"(src));
}
#define CP_COMMIT() asm volatile("cp.async.commit_group;")
#define CP_WAIT0()  asm volatile("cp.async.wait_group 0;")

// swizzle for 64-col (128B) bf16 rows
__device__ __forceinline__ uint32_t swz64(int row, int c) {
  return (uint32_t)(row*64 + ((c ^ (row & 7)) << 3));
}

// hi/lo pair writer
__device__ __forceinline__ void wr_pair(bf16* Dh, bf16* Dl, size_t off, float a, float b) {
  bf16 ha = __float2bfloat16_rn(a), hb = __float2bfloat16_rn(b);
  *(__nv_bfloat162*)&Dh[off] = __nv_bfloat162(ha, hb);
  *(__nv_bfloat162*)&Dl[off] = __nv_bfloat162(
      __float2bfloat16_rn(a - __bfloat162float(ha)),
      __float2bfloat16_rn(b - __bfloat162float(hb)));
}

// ---------------------------------------------------------------------------
// split_all
// ---------------------------------------------------------------------------
__device__ __forceinline__ void split_one(const float4* in, __nv_bfloat162* hp,
                                          __nv_bfloat162* lp, int i) {
  float4 v = in[i];
  bf16 hx = __float2bfloat16_rn(v.x), hy = __float2bfloat16_rn(v.y);
  bf16 hz = __float2bfloat16_rn(v.z), hw = __float2bfloat16_rn(v.w);
  hp[2*i]   = __nv_bfloat162(hx, hy);
  hp[2*i+1] = __nv_bfloat162(hz, hw);
  lp[2*i]   = __nv_bfloat162(__float2bfloat16_rn(v.x - __bfloat162float(hx)),
                             __float2bfloat16_rn(v.y - __bfloat162float(hy)));
  lp[2*i+1] = __nv_bfloat162(__float2bfloat16_rn(v.z - __bfloat162float(hz)),
                             __float2bfloat16_rn(v.w - __bfloat162float(hw)));
}

__global__ __launch_bounds__(256) void split_all(
    const float* __restrict__ x,  const float* __restrict__ Wq,
    const float* __restrict__ Wk, const float* __restrict__ Wv,
    const float* __restrict__ Wo,
    bf16* xh, bf16* xl, bf16* wqh, bf16* wql, bf16* wkh, bf16* wkl,
    bf16* wvh, bf16* wvl, bf16* woh, bf16* wol) {
  int g = blockIdx.x*256 + threadIdx.x;
  const int XQ = MROWS*D_/4;
  const int WQ = D_*D_/4;
  if (g < XQ) {
    split_one((const float4*)x, (__nv_bfloat162*)xh, (__nv_bfloat162*)xl, g);
  } else if (g < XQ + WQ) {
    split_one((const float4*)Wq, (__nv_bfloat162*)wqh, (__nv_bfloat162*)wql, g - XQ);
  } else if (g < XQ + 2*WQ) {
    split_one((const float4*)Wk, (__nv_bfloat162*)wkh, (__nv_bfloat162*)wkl, g - XQ - WQ);
  } else if (g < XQ + 3*WQ) {
    split_one((const float4*)Wv, (__nv_bfloat162*)wvh, (__nv_bfloat162*)wvl, g - XQ - 2*WQ);
  } else {
    split_one((const float4*)Wo, (__nv_bfloat162*)woh, (__nv_bfloat162*)wol, g - XQ - 3*WQ);
  }
}

// ---------------------------------------------------------------------------
// GEMM (3-pass bf16, cp.async, BK=64, 2-stage, 512 threads / 16 warps):
// CTA tile 256x128, warp tile 32x64. (R14/R15 proven, unchanged)
// ---------------------------------------------------------------------------
__device__ __forceinline__ void gemm_stage(uint32_t smb, int st,
    const bf16* gAh, const bf16* gAl, const bf16* gBh, const bf16* gBl,
    int kt, int tid) {
  const uint32_t base = smb + (uint32_t)st * 98304u;
  const uint32_t aH = base;
  const uint32_t aL = base + 32768u;
  const uint32_t bH = base + 65536u;
  const uint32_t bL = base + 81920u;
  const int kc = kt*64;
#pragma unroll
  for (int it = 0; it < 4; it++) {
    int ch = it*512 + tid;
    int row = ch >> 3, c = ch & 7;
    uint32_t off = swz64(row, c)*2;
    const size_t g = (size_t)row*D_ + kc + c*8;
    cpasync16(aH + off, gAh + g);
    cpasync16(aL + off, gAl + g);
  }
#pragma unroll
  for (int it = 0; it < 2; it++) {
    int ch = it*512 + tid;
    int row = ch >> 3, c = ch & 7;
    uint32_t off = swz64(row, c)*2;
    const size_t g = (size_t)row*D_ + kc + c*8;
    cpasync16(bH + off, gBh + g);
    cpasync16(bL + off, gBl + g);
  }
}

__device__ __forceinline__ void gemm_body(
    const bf16* Ah, const bf16* Al, const bf16* Bh, const bf16* Bl,
    int mode, float* C, bf16* Dh, bf16* Dl, float sq,
    int m0, int n0, bf16* smg, const float* s_invf) {
  const int tid = threadIdx.x;
  const int w = tid >> 5, lane = tid & 31;
  const int wm = w & 7, wn = w >> 3;
  const uint32_t smb = (uint32_t)__cvta_generic_to_shared(smg);

  const bf16* gAh = Ah + (size_t)m0*D_;
  const bf16* gAl = Al + (size_t)m0*D_;
  const bf16* gBh = Bh + (size_t)n0*D_;
  const bf16* gBl = Bl + (size_t)n0*D_;

  gemm_stage(smb, 0, gAh, gAl, gBh, gBl, 0, tid);
  CP_COMMIT();

  float acc[2][8][4];
#pragma unroll
  for (int m=0;m<2;m++)
#pragma unroll
    for (int n=0;n<8;n++)
#pragma unroll
      for (int e=0;e<4;e++) acc[m][n][e] = 0.f;

  const int arow = wm*32 + (lane & 15);
  const int ahalf = lane >> 4;
  const int brl = (lane & 7) + ((lane >> 4) << 3);
  const int bhalf = (lane >> 3) & 1;

  for (int kt = 0; kt < 16; kt++) {
    const int st = kt & 1;
    CP_WAIT0();
    __syncthreads();
    if (kt < 15) { gemm_stage(smb, st^1, gAh, gAl, gBh, gBl, kt+1, tid); CP_COMMIT(); }

    const uint32_t base = smb + (uint32_t)st * 98304u;
    const uint32_t aH = base;
    const uint32_t aL = base + 32768u;
    const uint32_t bH = base + 65536u;
    const uint32_t bL = base + 81920u;
#pragma unroll
    for (int ka = 0; ka < 4; ka++) {
      const int cca = ka*2 + ahalf;
      uint32_t ahf[2][4], alf[2][4];
#pragma unroll
      for (int i = 0; i < 2; i++) {
        ldsm4(aH + swz64(arow + 16*i, cca)*2, ahf[i]);
        ldsm4(aL + swz64(arow + 16*i, cca)*2, alf[i]);
      }
      const int ccb = ka*2 + bhalf;
      uint32_t bhf[8][2], blf[8][2];
#pragma unroll
      for (int pr = 0; pr < 4; pr++) {
        int rr = wn*64 + pr*16 + brl;
        uint32_t r4[4];
        ldsm4(bH + swz64(rr, ccb)*2, r4);
        bhf[2*pr][0]=r4[0]; bhf[2*pr][1]=r4[1]; bhf[2*pr+1][0]=r4[2]; bhf[2*pr+1][1]=r4[3];
        ldsm4(bL + swz64(rr, ccb)*2, r4);
        blf[2*pr][0]=r4[0]; blf[2*pr][1]=r4[1]; blf[2*pr+1][0]=r4[2]; blf[2*pr+1][1]=r4[3];
      }
#pragma unroll
      for (int n = 0; n < 8; n++)
#pragma unroll
        for (int i = 0; i < 2; i++)
          mma_bf16(acc[i][n], ahf[i], bhf[n]);
#pragma unroll
      for (int n = 0; n < 8; n++)
#pragma unroll
        for (int i = 0; i < 2; i++)
          mma_bf16(acc[i][n], ahf[i], blf[n]);
#pragma unroll
      for (int n = 0; n < 8; n++)
#pragma unroll
        for (int i = 0; i < 2; i++)
          mma_bf16(acc[i][n], alf[i], bhf[n]);
    }
  }

  const int g = lane >> 2, t2 = (lane & 3)*2;
  if (mode == 0) {
#pragma unroll
    for (int m = 0; m < 2; m++) {
      int row = m0 + wm*32 + m*16 + g;
#pragma unroll
      for (int n = 0; n < 8; n++) {
        int col = n0 + wn*64 + n*8 + t2;
        *(float2*)&C[(size_t)row*D_ + col]     = make_float2(acc[m][n][0], acc[m][n][1]);
        *(float2*)&C[(size_t)(row+8)*D_ + col] = make_float2(acc[m][n][2], acc[m][n][3]);
      }
    }
  } else if (mode == 1) {
#pragma unroll
    for (int m = 0; m < 2; m++) {
      int row = m0 + wm*32 + m*16 + g;
#pragma unroll
      for (int n = 0; n < 8; n++) {
        int col = n0 + wn*64 + n*8 + t2;
#pragma unroll
        for (int half = 0; half < 2; half++)
          wr_pair(Dh, Dl, (size_t)(row + half*8)*D_ + col,
                  acc[m][n][half*2], acc[m][n][half*2+1]);
      }
    }
  } else {
    const int hq = (n0 >> 6) + wn;
#pragma unroll
    for (int m = 0; m < 2; m++) {
      int row_l = m0 + wm*32 + m*16 + g;
#pragma unroll
      for (int half = 0; half < 2; half++) {
        int row = row_l + half*8;
        int b = row >> 11, s = row & 2047;
        size_t base = ((size_t)(b*16 + hq)*S_ + s) * KAD;
        float fs = (float)s;
#pragma unroll
        for (int n = 0; n < 4; n++) {
          int p0 = n*8 + t2;
          float t1a = acc[m][n][half*2],   t1b = acc[m][n][half*2+1];
          float u2a = acc[m][n+4][half*2], u2b = acc[m][n+4][half*2+1];
          float sna, csa, snb, csb;
          sincosf(fs * s_invf[p0],   &sna, &csa);
          sincosf(fs * s_invf[p0+1], &snb, &csb);
          float r1a = t1a*csa - u2a*sna, r2a = u2a*csa + t1a*sna;
          float r1b = t1b*csb - u2b*snb, r2b = u2b*csb + t1b*snb;
          wr_pair(Dh, Dl, base + p0,        r1a,          r1b);
          wr_pair(Dh, Dl, base + p0 + 32,   r2a,          r2b);
          wr_pair(Dh, Dl, base + 64 + p0,   sq*r1a*r1a,   sq*r1b*r1b);
          wr_pair(Dh, Dl, base + 96 + p0,   sq*r2a*r2a,   sq*r2b*r2b);
        }
      }
    }
  }
}

__global__ __launch_bounds__(512) void gemm_qkv(
    const bf16* __restrict__ xh, const bf16* __restrict__ xl,
    const bf16* __restrict__ wqh, const bf16* __restrict__ wql,
    const bf16* __restrict__ wkh, const bf16* __restrict__ wkl,
    const bf16* __restrict__ wvh, const bf16* __restrict__ wvl,
    bf16* __restrict__ qah, bf16* __restrict__ qal,
    bf16* __restrict__ kah, bf16* __restrict__ kal,
    bf16* __restrict__ vh, bf16* __restrict__ vl) {
  extern __shared__ __align__(16) bf16 smg[];
  __shared__ float s_invf[32];
  if (threadIdx.x < 32)
    s_invf[threadIdx.x] = (float)(1.0 / pow(10000.0, (double)threadIdx.x / 32.0));
  int m0 = blockIdx.x * 256, n0 = blockIdx.y * 128;
  int z = blockIdx.z;
  if (z == 0)
    gemm_body(xh, xl, wqh, wql, 2, nullptr, qah, qal, 1.0f, m0, n0, smg, s_invf);
  else if (z == 1)
    gemm_body(xh, xl, wkh, wkl, 2, nullptr, kah, kal, 0.1f, m0, n0, smg, s_invf);
  else
    gemm_body(xh, xl, wvh, wvl, 1, nullptr, vh, vl, 0.f, m0, n0, smg, nullptr);
}

__global__ __launch_bounds__(512) void gemm_o(
    const bf16* __restrict__ mh, const bf16* __restrict__ ml,
    const bf16* __restrict__ woh, const bf16* __restrict__ wol,
    float* __restrict__ out) {
  extern __shared__ __align__(16) bf16 smg[];
  gemm_body(mh, ml, woh, wol, 0, out, nullptr, nullptr, 0.f,
            blockIdx.x * 256, blockIdx.y * 128, smg, nullptr);
}

// ---------------------------------------------------------------------------
// Flash attention v6: fixed-shift softmax + software-pipelined fragment loads
// (double-buffered K/V register fragments hide ldsm latency under mma).
// 128 q/CTA, kv 128, 3-pass bf16, 2-stage cp.async, fused gate-merge.
// ---------------------------------------------------------------------------
#define FST 49152

__device__ __forceinline__ void flash_stage(uint32_t smb, int st, int tid,
    const bf16* kgh_b, const bf16* kgl_b, const bf16* vgh, const bf16* vgl, int kb) {
  const uint32_t KH = smb + (uint32_t)(st*FST)*2;
  const uint32_t KL = KH + 16384*2;
  const uint32_t VH = KH + 32768*2;
  const uint32_t VL = KH + 40960*2;
  const bf16* kgh = kgh_b + (size_t)kb*128*KAD;
  const bf16* kgl = kgl_b + (size_t)kb*128*KAD;
#pragma unroll
  for (int it = 0; it < 8; it++) {
    int idx = it*256 + tid;
    int r = idx >> 4, c = idx & 15;
    uint32_t off = (uint32_t)(r*128 + ((c ^ (r & 7)) << 3))*2;
    cpasync16(KH + off, kgh + idx*8);
    cpasync16(KL + off, kgl + idx*8);
  }
#pragma unroll
  for (int it = 0; it < 4; it++) {
    int idx = it*256 + tid;
    int r = idx >> 3, c = idx & 7;
    uint32_t off = (uint32_t)(r*64 + ((c ^ (r & 7)) << 3))*2;
    size_t goff = (size_t)(kb*128 + r)*D_ + c*8;
    cpasync16(VH + off, vgh + goff);
    cpasync16(VL + off, vgl + goff);
  }
}

// load K fragments for micro-iteration it = ka*2 + jh
__device__ __forceinline__ void load_kfrag(uint32_t KH, uint32_t KL, int it,
    int brl, int bhalf, uint32_t bhf[8][2], uint32_t blf[8][2]) {
  const int ka = it >> 1, jh = it & 1;
#pragma unroll
  for (int pr = 0; pr < 4; pr++) {
    int rr = jh*64 + pr*16 + brl;
    int c = ka*2 + bhalf;
    uint32_t off = (uint32_t)(rr*128 + ((c ^ (rr & 7)) << 3))*2;
    uint32_t r4[4];
    ldsm4(KH + off, r4);
    bhf[2*pr][0]=r4[0]; bhf[2*pr][1]=r4[1]; bhf[2*pr+1][0]=r4[2]; bhf[2*pr+1][1]=r4[3];
    ldsm4(KL + off, r4);
    blf[2*pr][0]=r4[0]; blf[2*pr][1]=r4[1]; blf[2*pr+1][0]=r4[2]; blf[2*pr+1][1]=r4[3];
  }
}

// load V fragments for kt
__device__ __forceinline__ void load_vfrag(uint32_t VH, uint32_t VL, int kt,
    int lane, uint32_t vhf[8][2], uint32_t vlf[8][2]) {
  int vr = kt*16 + (lane & 7) + ((lane >> 3) & 1)*8;
#pragma unroll
  for (int pr = 0; pr < 4; pr++) {
    int c = pr*2 + (lane >> 4);
    uint32_t off = (uint32_t)(vr*64 + ((c ^ (vr & 7)) << 3))*2;
    uint32_t r4[4];
    ldsm4t(VH + off, r4);
    vhf[2*pr][0]=r4[0]; vhf[2*pr][1]=r4[1]; vhf[2*pr+1][0]=r4[2]; vhf[2*pr+1][1]=r4[3];
    ldsm4t(VL + off, r4);
    vlf[2*pr][0]=r4[0]; vlf[2*pr][1]=r4[1]; vlf[2*pr+1][0]=r4[2]; vlf[2*pr+1][1]=r4[3];
  }
}

__global__ __launch_bounds__(256) void flash_bf16(
    const bf16* __restrict__ Qh, const bf16* __restrict__ Ql,
    const bf16* __restrict__ Kh, const bf16* __restrict__ Kl,
    const bf16* __restrict__ Vh, const bf16* __restrict__ Vl,
    const float* __restrict__ gate,
    bf16* __restrict__ Mh, bf16* __restrict__ Ml) {
  extern __shared__ __align__(16) bf16 sm[];
  const int bh = blockIdx.y;
  const int qi = (int)gridDim.x - 1 - (int)blockIdx.x;
  const int b = bh >> 4, h = bh & 15;
  const int tid = threadIdx.x, w = tid >> 5, lane = tid & 31;
  const uint32_t smb = (uint32_t)__cvta_generic_to_shared(sm);

  const uint4* qgh = (const uint4*)(Qh + ((size_t)bh*S_ + (size_t)qi*128) * KAD);
  const uint4* qgl = (const uint4*)(Ql + ((size_t)bh*S_ + (size_t)qi*128) * KAD);
#pragma unroll
  for (int it = 0; it < 8; it++) {
    int idx = it*256 + tid;
    int r = idx >> 4, c = idx & 15;
    uint32_t off = r*128 + ((c ^ (r & 7)) << 3);
    *(uint4*)&sm[off]         = qgh[idx];
    *(uint4*)&sm[16384 + off] = qgl[idx];
  }
  __syncthreads();

  uint32_t qfh[8][4], qfl[8][4];
  {
    int r = w*16 + (lane & 15);
#pragma unroll
    for (int ka = 0; ka < 8; ka++) {
      int c = ka*2 + (lane >> 4);
      uint32_t off = (uint32_t)(r*128 + ((c ^ (r & 7)) << 3));
      ldsm4(smb + off*2, qfh[ka]);
      ldsm4(smb + (16384 + off)*2, qfl[ka]);
    }
  }
  __syncthreads();

  float l0 = 0.f, l1 = 0.f;
  float oacc[8][4];
#pragma unroll
  for (int j=0;j<8;j++)
#pragma unroll
    for (int e=0;e<4;e++) oacc[j][e] = 0.f;

  const int nkv = qi + 1;
  const int rg0 = qi*128 + w*16 + (lane >> 2);
  const bf16* kgh_b = Kh + (size_t)bh*S_*KAD;
  const bf16* kgl_b = Kl + (size_t)bh*S_*KAD;
  const bf16* vgh = Vh + ((size_t)b*S_)*D_ + h*HD;
  const bf16* vgl = Vl + ((size_t)b*S_)*D_ + h*HD;

  flash_stage(smb, 0, tid, kgh_b, kgl_b, vgh, vgl, 0);
  CP_COMMIT();

  const int brl = (lane & 7) + ((lane >> 4) << 3);
  const int bhalf = (lane >> 3) & 1;

  for (int kb = 0; kb < nkv; kb++) {
    const int st = kb & 1;
    CP_WAIT0();
    __syncthreads();
    if (kb + 1 < nkv) { flash_stage(smb, st^1, tid, kgh_b, kgl_b, vgh, vgl, kb+1); CP_COMMIT(); }

    const uint32_t KH = smb + (uint32_t)(st*FST)*2;
    const uint32_t KL = KH + 16384*2;
    const uint32_t VH = KH + 32768*2;
    const uint32_t VL = KH + 40960*2;

    // ---- S = Q . K^T, software-pipelined fragment loads ----
    float sacc[16][4];
#pragma unroll
    for (int j=0;j<16;j++)
#pragma unroll
      for (int e=0;e<4;e++) sacc[j][e] = 0.f;

    uint32_t kfh[2][8][2], kfl[2][8][2];
    load_kfrag(KH, KL, 0, brl, bhalf, kfh[0], kfl[0]);
#pragma unroll
    for (int it = 0; it < 16; it++) {
      const int cur = it & 1;
      if (it < 15) load_kfrag(KH, KL, it+1, brl, bhalf, kfh[cur^1], kfl[cur^1]);
      const int ka = it >> 1, jh = it & 1;
      // per-accumulator pass order unchanged (hi*hi, hi*lo, lo*hi)
#pragma unroll
      for (int j = 0; j < 8; j++) mma_bf16(sacc[jh*8+j], qfh[ka], kfh[cur][j]);
#pragma unroll
      for (int j = 0; j < 8; j++) mma_bf16(sacc[jh*8+j], qfh[ka], kfl[cur][j]);
#pragma unroll
      for (int j = 0; j < 8; j++) mma_bf16(sacc[jh*8+j], qfl[ka], kfh[cur][j]);
    }

    // fixed-shift exp: p = exp(S*0.125 - MSHIFT); masked entries exactly 0
    if (kb == nkv - 1) {
#pragma unroll
      for (int j = 0; j < 16; j++)
#pragma unroll
        for (int e = 0; e < 4; e++) {
          int row = rg0 + ((e >= 2) ? 8 : 0);
          int col = kb*128 + j*8 + (lane & 3)*2 + (e & 1);
          float p = __expf(fmaf(sacc[j][e], 0.125f, -MSHIFT));
          sacc[j][e] = (col > row) ? 0.f : p;
        }
    } else {
#pragma unroll
      for (int j = 0; j < 16; j++)
#pragma unroll
        for (int e = 0; e < 4; e++)
          sacc[j][e] = __expf(fmaf(sacc[j][e], 0.125f, -MSHIFT));
    }
#pragma unroll
    for (int j = 0; j < 16; j++) {
      l0 += sacc[j][0] + sacc[j][1];
      l1 += sacc[j][2] + sacc[j][3];
    }

    // P fragments (bf16 hi + lo residual)
    uint32_t pfh[8][4], pfl[8][4];
#pragma unroll
    for (int kt = 0; kt < 8; kt++) {
      int j0 = 2*kt, j1 = 2*kt + 1;
      float p[8] = { sacc[j0][0], sacc[j0][1], sacc[j0][2], sacc[j0][3],
                     sacc[j1][0], sacc[j1][1], sacc[j1][2], sacc[j1][3] };
      float pl[8];
#pragma unroll
      for (int e = 0; e < 8; e++) {
        float hh = __bfloat162float(__float2bfloat16_rn(p[e]));
        pl[e] = p[e] - hh;
      }
      pfh[kt][0] = packbf(p[0], p[1]);  pfh[kt][1] = packbf(p[2], p[3]);
      pfh[kt][2] = packbf(p[4], p[5]);  pfh[kt][3] = packbf(p[6], p[7]);
      pfl[kt][0] = packbf(pl[0], pl[1]); pfl[kt][1] = packbf(pl[2], pl[3]);
      pfl[kt][2] = packbf(pl[4], pl[5]); pfl[kt][3] = packbf(pl[6], pl[7]);
    }

    // ---- O += P . V, software-pipelined V fragment loads ----
    uint32_t vfh[2][8][2], vfl[2][8][2];
    load_vfrag(VH, VL, 0, lane, vfh[0], vfl[0]);
#pragma unroll
    for (int kt = 0; kt < 8; kt++) {
      const int cur = kt & 1;
      if (kt < 7) load_vfrag(VH, VL, kt+1, lane, vfh[cur^1], vfl[cur^1]);
#pragma unroll
      for (int j = 0; j < 8; j++) mma_bf16(oacc[j], pfh[kt], vfh[cur][j]);
#pragma unroll
      for (int j = 0; j < 8; j++) mma_bf16(oacc[j], pfh[kt], vfl[cur][j]);
#pragma unroll
      for (int j = 0; j < 8; j++) mma_bf16(oacc[j], pfl[kt], vfh[cur][j]);
    }
  }

  // epilogue: reduce l across quad lanes once, normalize, gate-merge, store
  l0 += __shfl_xor_sync(0xffffffffu, l0, 1);
  l0 += __shfl_xor_sync(0xffffffffu, l0, 2);
  l1 += __shfl_xor_sync(0xffffffffu, l1, 1);
  l1 += __shfl_xor_sync(0xffffffffu, l1, 2);
  float inv0 = 1.f / l0, inv1 = 1.f / l1;
  int r0 = qi*128 + w*16 + (lane >> 2);
  int srow0 = b*S_ + r0;
#pragma unroll
  for (int j = 0; j < 8; j++) {
    int d = j*8 + (lane & 3)*2;
    float g0 = gate[d], g1 = gate[d+1];
#pragma unroll
    for (int half = 0; half < 2; half++) {
      float inv = half ? inv1 : inv0;
      float o0 = oacc[j][half*2]   * inv;
      float o1 = oacc[j][half*2+1] * inv;
      float v0 = o0 + 0.05f*o0*o0*g0;
      float v1 = o1 + 0.05f*o1*o1*g1;
      wr_pair(Mh, Ml, (size_t)(srow0 + half*8)*D_ + h*HD + d, v0, v1);
    }
  }
}

extern "C" void kernel_launch(void* const* d_in, const int* in_sizes, int n_in,
                              void* d_out, int out_size) {
  const float* x  = (const float*)d_in[0];
  const float* Wq = (const float*)d_in[1];
  const float* Wk = (const float*)d_in[2];
  const float* Wv = (const float*)d_in[3];
  const float* Wo = (const float*)d_in[4];
  const float* gw = (const float*)d_in[5];
  float* out = (float*)d_out;

  bf16 *xh,*xl,*wqh,*wql,*wkh,*wkl,*wvh,*wvl,*woh,*wol;
  bf16 *qah,*qal,*kah,*kal,*vh,*vl,*mh,*ml;
  cudaGetSymbolAddress((void**)&xh, g_xh); cudaGetSymbolAddress((void**)&xl, g_xl);
  cudaGetSymbolAddress((void**)&wqh, g_wqh); cudaGetSymbolAddress((void**)&wql, g_wql);
  cudaGetSymbolAddress((void**)&wkh, g_wkh); cudaGetSymbolAddress((void**)&wkl, g_wkl);
  cudaGetSymbolAddress((void**)&wvh, g_wvh); cudaGetSymbolAddress((void**)&wvl, g_wvl);
  cudaGetSymbolAddress((void**)&woh, g_woh); cudaGetSymbolAddress((void**)&wol, g_wol);
  cudaGetSymbolAddress((void**)&qah, g_qah); cudaGetSymbolAddress((void**)&qal, g_qal);
  cudaGetSymbolAddress((void**)&kah, g_kah); cudaGetSymbolAddress((void**)&kal, g_kal);
  cudaGetSymbolAddress((void**)&vh, g_vh);   cudaGetSymbolAddress((void**)&vl, g_vl);
  cudaGetSymbolAddress((void**)&mh, g_mh);   cudaGetSymbolAddress((void**)&ml, g_ml);

  cudaFuncSetAttribute(gemm_qkv, cudaFuncAttributeMaxDynamicSharedMemorySize, 196608);
  cudaFuncSetAttribute(gemm_o,   cudaFuncAttributeMaxDynamicSharedMemorySize, 196608);
  cudaFuncSetAttribute(flash_bf16, cudaFuncAttributeMaxDynamicSharedMemorySize, 196608);

  split_all<<<8192, 256>>>(x, Wq, Wk, Wv, Wo,
                           xh, xl, wqh, wql, wkh, wkl, wvh, wvl, woh, wol);

  gemm_qkv<<<dim3(16, 8, 3), 512, 196608>>>(xh, xl, wqh, wql, wkh, wkl, wvh, wvl,
                                            qah, qal, kah, kal, vh, vl);

  flash_bf16<<<dim3(16, 32), 256, 196608>>>(qah, qal, kah, kal, vh, vl, gw, mh, ml);

  gemm_o<<<dim3(16, 8), 512, 196608>>>(mh, ml, woh, wol, out);
}